// round 6
// baseline (speedup 1.0000x reference)
#include <cuda_runtime.h>

// ---------------- problem constants ----------------
#define BB    64    // batch
#define NNv   64    // news per batch
#define HLv   50    // history length
#define INv   384   // input dim
#define POSv  64    // pos-emb dim
#define ATTv  256   // attention hidden dim
#define NEWSv 448   // IN + POS
#define W1LD  896   // W1 row stride (2*NEWS)

typedef unsigned long long u64;

// packed f32x2 helpers (Blackwell 2x fp32 path; ptxas never emits these from C++)
#define FMA2(d, a, b, c) \
    asm("fma.rn.f32x2 %0, %1, %2, %3;" : "=l"(d) : "l"(a), "l"(b), "l"(c))
#define PACK2(d, lo, hi) \
    asm("mov.b64 %0, {%1, %2};" : "=l"(d) : "f"(lo), "f"(hi))
#define UNPACK2(lo, hi, s) \
    asm("mov.b64 {%0, %1}, %2;" : "=f"(lo), "=f"(hi) : "l"(s))

// ---------------- device scratch (no allocations allowed) ----------------
__device__ float g_PN[BB * NNv * ATTv];    // 4 MB  : pn + t0   [4096, 256]
__device__ float g_PL[BB * HLv * ATTv];    // 3.3 MB: pl + posW [3200, 256]
__device__ float g_t0[ATTv];               // b1 + pos0 @ Wn_pos
__device__ float g_posW[HLv * ATTv];       // pos_emb[1+h] @ Wl_pos

__device__ __forceinline__ float tanh_fast(float x) {
    float y;
    asm("tanh.approx.f32 %0, %1;" : "=f"(y) : "f"(x));
    return y;
}

// ---------------- K0: tiny precompute of t0 and posW ----------------
__global__ void prep_kernel(const float* __restrict__ pos_emb,
                            const float* __restrict__ W1,
                            const float* __restrict__ b1) {
    int a = threadIdx.x;  // 0..255
    if (blockIdx.x == 0) {
        float s = b1[a];
#pragma unroll
        for (int j = 0; j < POSv; j++)
            s += pos_emb[j] * W1[a * W1LD + INv + j];
        g_t0[a] = s;
    } else {
        int h = blockIdx.x - 1;  // 0..49
        float s = 0.f;
#pragma unroll
        for (int j = 0; j < POSv; j++)
            s += pos_emb[(1 + h) * POSv + j] * W1[a * W1LD + NEWSv + INv + j];
        g_posW[h * ATTv + a] = s;
    }
}

// ---------------- K1: nf output (pure copy/broadcast, float4) ----------------
__global__ void nf_kernel(const float4* __restrict__ news4,
                          const float4* __restrict__ pos4,
                          float4* __restrict__ out4) {
    int bn = blockIdx.x;      // 0..4095
    int d4 = threadIdx.x;     // 0..111  (112 float4 = 448 floats)
    if (d4 >= NEWSv / 4) return;
    float4 v = (d4 < INv / 4) ? news4[bn * (INv / 4) + d4] : pos4[d4 - INv / 4];
    out4[bn * (NEWSv / 4) + d4] = v;
}

// ---------------- K2: fused GEMMs with packed f32x2 FMA --------------------
// C[m,a] = sum_k A[m,k] * W1[a, colofs+k] + bias.  z=0: PN, z=1: PL.
// BM=BN=64, BK=16, 256 threads. Per thread: rows i=0..3 (m), packed col pairs.
// A tile stored DUPLICATED (As2[k][2m]=As2[k][2m+1]=A[m,k]) so the scalar
// multiplicand is a broadcast LDS.64; B pair is a contiguous LDS.64.
__global__ __launch_bounds__(256) void gemm_kernel(const float* __restrict__ news,
                                                   const float* __restrict__ logv,
                                                   const float* __restrict__ W1) {
    const int isPL = blockIdx.z;
    const float* A;
    float* C;
    int colofs;
    if (isPL) {
        if (blockIdx.y >= 50) return;  // PL has only 3200/64 = 50 row-blocks
        A = logv; C = g_PL; colofs = NEWSv;
    } else {
        A = news; C = g_PN; colofs = 0;
    }
    const int m0 = blockIdx.y * 64;
    const int n0 = blockIdx.x * 64;

    __shared__ __align__(16) float As2[16][136];  // duplicated: [k][2m..2m+1]
    __shared__ __align__(16) float Bs[16][68];    // transposed: [k][a]

    const int tid = threadIdx.x;
    const int tx = tid & 15, ty = tid >> 4;
    const int lr = tid >> 2, lc = tid & 3;   // loader: row, 4-float col group

    u64 acc[4][2];
#pragma unroll
    for (int i = 0; i < 4; i++) { acc[i][0] = 0ull; acc[i][1] = 0ull; }

    const float* Aptr = A  + (m0 + lr) * INv  + lc * 4;
    const float* Bptr = W1 + (n0 + lr) * W1LD + colofs + lc * 4;

    for (int k0 = 0; k0 < INv; k0 += 16) {
        float4 av = *(const float4*)(Aptr + k0);
        float4 bv = *(const float4*)(Bptr + k0);
        As2[lc * 4 + 0][2 * lr] = av.x; As2[lc * 4 + 0][2 * lr + 1] = av.x;
        As2[lc * 4 + 1][2 * lr] = av.y; As2[lc * 4 + 1][2 * lr + 1] = av.y;
        As2[lc * 4 + 2][2 * lr] = av.z; As2[lc * 4 + 2][2 * lr + 1] = av.z;
        As2[lc * 4 + 3][2 * lr] = av.w; As2[lc * 4 + 3][2 * lr + 1] = av.w;
        Bs[lc * 4 + 0][lr] = bv.x; Bs[lc * 4 + 1][lr] = bv.y;
        Bs[lc * 4 + 2][lr] = bv.z; Bs[lc * 4 + 3][lr] = bv.w;
        __syncthreads();
#pragma unroll
        for (int k = 0; k < 16; k++) {
            u64 b01 = *(const u64*)&Bs[k][tx * 4];
            u64 b23 = *(const u64*)&Bs[k][tx * 4 + 2];
#pragma unroll
            for (int i = 0; i < 4; i++) {
                u64 ad = *(const u64*)&As2[k][(ty * 4 + i) * 2];  // (A, A)
                FMA2(acc[i][0], ad, b01, acc[i][0]);
                FMA2(acc[i][1], ad, b23, acc[i][1]);
            }
        }
        __syncthreads();
    }

#pragma unroll
    for (int i = 0; i < 4; i++) {
        int m = m0 + ty * 4 + i;
        const float* biasp = isPL ? (g_posW + (m % HLv) * ATTv) : g_t0;
        float c0, c1, c2, c3;
        UNPACK2(c0, c1, acc[i][0]);
        UNPACK2(c2, c3, acc[i][1]);
        int a = n0 + tx * 4;
        C[m * ATTv + a + 0] = c0 + biasp[a + 0];
        C[m * ATTv + a + 1] = c1 + biasp[a + 1];
        C[m * ATTv + a + 2] = c2 + biasp[a + 2];
        C[m * ATTv + a + 3] = c3 + biasp[a + 3];
    }
}

// ---------------- K3: logits + softmax + output GEMM -----------------------
// One CTA per (b, 4 n's) -> grid 1024 for occupancy. Unmasked-h compaction
// balances warps; output GEMM uses packed f32x2 with a pipelined load buffer.
#define N_PER_CTA 4

__global__ __launch_bounds__(256) void attn_kernel(const float* __restrict__ logv,
                                                   const int*   __restrict__ mask,
                                                   const float* __restrict__ pos_emb,
                                                   const float* __restrict__ W2,
                                                   const float* __restrict__ b2,
                                                   float* __restrict__ out) {
    const int b = blockIdx.y;
    const int nbase = blockIdx.x * N_PER_CTA;

    __shared__ __align__(16) float pnS[N_PER_CTA][ATTv];    // 4 KB
    __shared__ float logitS[N_PER_CTA][HLv + 2];
    __shared__ __align__(8) float attnPf[HLv][N_PER_CTA];   // n-major for u64 loads
    __shared__ int maskS[HLv];
    __shared__ short listS[HLv];
    __shared__ int cntS;

    const int tid = threadIdx.x;
    const int w = tid >> 5, lane = tid & 31;

    // pn tile: 4 rows x 256 = 256 float4, one per thread
    ((float4*)&pnS[0][0])[tid] =
        ((const float4*)(g_PN + (size_t)(b * NNv + nbase) * ATTv))[tid];
    if (tid < HLv) maskS[tid] = mask[b * HLv + tid];

    float w2r[8];
#pragma unroll
    for (int i = 0; i < 8; i++) w2r[i] = W2[lane + 32 * i];
    const float b2v = b2[0];
    __syncthreads();

    // compact unmasked h list (thread 0); others init masked logits
    if (tid == 0) {
        int c = 0;
        for (int h = 0; h < HLv; h++)
            if (maskS[h] != 0) listS[c++] = (short)h;
        cntS = c;
    }
    if (tid < HLv && maskS[tid] == 0) {
#pragma unroll
        for (int n = 0; n < N_PER_CTA; n++) logitS[n][tid] = -1e9f;
    }
    __syncthreads();
    const int cnt = cntS;

    // ---- logits over compacted h: balanced across 8 warps ----
    for (int idx = w; idx < cnt; idx += 8) {
        const int h = listS[idx];
        const float* pl = g_PL + (size_t)(b * HLv + h) * ATTv;
        float plr[8];
#pragma unroll
        for (int i = 0; i < 8; i++) plr[i] = pl[lane + 32 * i];  // coalesced

        float s[N_PER_CTA];
#pragma unroll
        for (int n = 0; n < N_PER_CTA; n++) s[n] = 0.f;
#pragma unroll
        for (int i = 0; i < 8; i++) {
            const float pv = plr[i];
            const float wv = w2r[i];
            const int a = lane + 32 * i;
#pragma unroll
            for (int n = 0; n < N_PER_CTA; n++)
                s[n] += wv * tanh_fast(pv + pnS[n][a]);
        }
#pragma unroll
        for (int n = 0; n < N_PER_CTA; n++) {
            float v = s[n];
#pragma unroll
            for (int o = 16; o > 0; o >>= 1) v += __shfl_xor_sync(0xffffffffu, v, o);
            if (lane == 0) logitS[n][h] = v + b2v;
        }
    }
    __syncthreads();

    // ---- softmax: warp n (n<4) handles row n. All-masked -> uniform (jax). ----
    if (w < N_PER_CTA) {
        float v0 = logitS[w][lane];
        bool has1 = (lane + 32) < HLv;
        float v1 = has1 ? logitS[w][lane + 32] : -1e30f;
        float mx = fmaxf(v0, v1);
#pragma unroll
        for (int o = 16; o > 0; o >>= 1) mx = fmaxf(mx, __shfl_xor_sync(0xffffffffu, mx, o));
        float e0 = __expf(v0 - mx);
        float e1 = has1 ? __expf(v1 - mx) : 0.f;
        float ssum = e0 + e1;
#pragma unroll
        for (int o = 16; o > 0; o >>= 1) ssum += __shfl_xor_sync(0xffffffffu, ssum, o);
        float inv = 1.f / ssum;
        attnPf[lane][w] = e0 * inv;
        if (has1) attnPf[lane + 32][w] = e1 * inv;
    }
    __syncthreads();

    // ---- output: out[b, nbase+n, d] = sum_h attn[n,h] * lf[b,h,d] ----
    // lf[b,h,d] = d<384 ? log_vec[b,h,d] : pos_emb[1+h, d-384] (never materialized)
    for (int d = tid; d < NEWSv; d += 256) {
        u64 acc01 = 0ull, acc23 = 0ull;
        const float* srcp;
        int stride;
        if (d < INv) { srcp = logv + (size_t)b * HLv * INv + d; stride = INv; }
        else         { srcp = pos_emb + POSv + (d - INv);       stride = POSv; }

        float lv[10], lvn[10];
#pragma unroll
        for (int u = 0; u < 10; u++) lv[u] = srcp[u * stride];
#pragma unroll
        for (int h0 = 0; h0 < HLv; h0 += 10) {
            if (h0 + 10 < HLv) {
#pragma unroll
                for (int u = 0; u < 10; u++) lvn[u] = srcp[(h0 + 10 + u) * stride];
            }
#pragma unroll
            for (int u = 0; u < 10; u++) {
                const int h = h0 + u;
                u64 lvd;
                PACK2(lvd, lv[u], lv[u]);
                u64 p01 = *(const u64*)&attnPf[h][0];
                u64 p23 = *(const u64*)&attnPf[h][2];
                FMA2(acc01, lvd, p01, acc01);
                FMA2(acc23, lvd, p23, acc23);
            }
#pragma unroll
            for (int u = 0; u < 10; u++) lv[u] = lvn[u];
        }
        float r0, r1, r2, r3;
        UNPACK2(r0, r1, acc01);
        UNPACK2(r2, r3, acc23);
        float* op = out + (size_t)(b * NNv + nbase) * NEWSv + d;
        op[0 * NEWSv] = r0;
        op[1 * NEWSv] = r1;
        op[2 * NEWSv] = r2;
        op[3 * NEWSv] = r3;
    }
}

// ---------------- launch ----------------
extern "C" void kernel_launch(void* const* d_in, const int* in_sizes, int n_in,
                              void* d_out, int out_size) {
    const float* logv = (const float*)d_in[0];   // [64,50,384]
    const int*   mask = (const int*)  d_in[1];   // [64,50]
    const float* news = (const float*)d_in[2];   // [64,64,384]
    const float* pos  = (const float*)d_in[3];   // [100,64]
    const float* W1   = (const float*)d_in[4];   // [256,896]
    const float* b1   = (const float*)d_in[5];   // [256]
    const float* W2   = (const float*)d_in[6];   // [1,256]
    const float* b2   = (const float*)d_in[7];   // [1]

    float* out_user = (float*)d_out;                       // [64,64,448]
    float* out_nf   = out_user + (size_t)BB * NNv * NEWSv; // [64,64,448]

    prep_kernel<<<51, 256>>>(pos, W1, b1);
    nf_kernel<<<BB * NNv, 128>>>((const float4*)news, (const float4*)pos,
                                 (float4*)out_nf);
    gemm_kernel<<<dim3(4, 64, 2), 256>>>(news, logv, W1);
    attn_kernel<<<dim3(NNv / N_PER_CTA, BB), 256>>>(logv, mask, pos, W2, b2, out_user);
}

// round 11
// speedup vs baseline: 1.2896x; 1.2896x over previous
#include <cuda_runtime.h>

// ---------------- problem constants ----------------
#define BB    64    // batch
#define NNv   64    // news per batch
#define HLv   50    // history length
#define INv   384   // input dim
#define POSv  64    // pos-emb dim
#define ATTv  256   // attention hidden dim
#define NEWSv 448   // IN + POS
#define W1LD  896   // W1 row stride (2*NEWS)

// ---------------- device scratch (no allocations allowed) ----------------
__device__ float g_PN[BB * NNv * ATTv];    // 4 MB  : pn + t0   [4096, 256]
__device__ float g_PL[BB * HLv * ATTv];    // 3.3 MB: pl + posW [3200, 256]
__device__ float g_t0[ATTv];               // b1 + pos0 @ Wn_pos
__device__ float g_posW[HLv * ATTv];       // pos_emb[1+h] @ Wl_pos

__device__ __forceinline__ float tanh_fast(float x) {
    float y;
    asm("tanh.approx.f32 %0, %1;" : "=f"(y) : "f"(x));
    return y;
}

// ---------------- K0: tiny precompute of t0 and posW ----------------
__global__ void prep_kernel(const float* __restrict__ pos_emb,
                            const float* __restrict__ W1,
                            const float* __restrict__ b1) {
    int a = threadIdx.x;  // 0..255
    if (blockIdx.x == 0) {
        float s = b1[a];
#pragma unroll
        for (int j = 0; j < POSv; j++)
            s += pos_emb[j] * W1[a * W1LD + INv + j];
        g_t0[a] = s;
    } else {
        int h = blockIdx.x - 1;  // 0..49
        float s = 0.f;
#pragma unroll
        for (int j = 0; j < POSv; j++)
            s += pos_emb[(1 + h) * POSv + j] * W1[a * W1LD + NEWSv + INv + j];
        g_posW[h * ATTv + a] = s;
    }
}

// ---------------- K1: nf output (pure copy/broadcast, float4) ----------------
__global__ void nf_kernel(const float4* __restrict__ news4,
                          const float4* __restrict__ pos4,
                          float4* __restrict__ out4) {
    int bn = blockIdx.x;      // 0..4095
    int d4 = threadIdx.x;     // 0..111  (112 float4 = 448 floats)
    if (d4 >= NEWSv / 4) return;
    float4 v = (d4 < INv / 4) ? news4[bn * (INv / 4) + d4] : pos4[d4 - INv / 4];
    out4[bn * (NEWSv / 4) + d4] = v;
}

// ---------------- K2: fused FFMA GEMMs  (z=0: PN, z=1: PL) ----------------
// C[m,a] = sum_k A[m,k] * W1[a, colofs+k]  + bias
// Tiles: BM=BN=64, BK=16, 256 threads, 4x4 register blocking. (R5 version —
// at the scalar FFMA roofline; FMA2 variant regressed in R6.)
__global__ __launch_bounds__(256) void gemm_kernel(const float* __restrict__ news,
                                                   const float* __restrict__ logv,
                                                   const float* __restrict__ W1) {
    const int isPL = blockIdx.z;
    const float* A;
    float* C;
    int colofs;
    if (isPL) {
        if (blockIdx.y >= 50) return;  // PL has only 3200/64 = 50 row-blocks
        A = logv; C = g_PL; colofs = NEWSv;
    } else {
        A = news; C = g_PN; colofs = 0;
    }
    const int m0 = blockIdx.y * 64;
    const int n0 = blockIdx.x * 64;

    __shared__ __align__(16) float As[16][68];  // transposed: As[k][m]
    __shared__ __align__(16) float Bs[16][68];  // transposed: Bs[k][a]

    const int tid = threadIdx.x;
    const int tx = tid & 15, ty = tid >> 4;
    const int lr = tid >> 2, lc = tid & 3;   // loader: row, 4-float col group

    float acc[4][4];
#pragma unroll
    for (int i = 0; i < 4; i++)
#pragma unroll
        for (int j = 0; j < 4; j++) acc[i][j] = 0.f;

    const float* Aptr = A  + (m0 + lr) * INv  + lc * 4;
    const float* Bptr = W1 + (n0 + lr) * W1LD + colofs + lc * 4;

    for (int k0 = 0; k0 < INv; k0 += 16) {
        float4 av = *(const float4*)(Aptr + k0);
        float4 bv = *(const float4*)(Bptr + k0);
        As[lc * 4 + 0][lr] = av.x; As[lc * 4 + 1][lr] = av.y;
        As[lc * 4 + 2][lr] = av.z; As[lc * 4 + 3][lr] = av.w;
        Bs[lc * 4 + 0][lr] = bv.x; Bs[lc * 4 + 1][lr] = bv.y;
        Bs[lc * 4 + 2][lr] = bv.z; Bs[lc * 4 + 3][lr] = bv.w;
        __syncthreads();
#pragma unroll
        for (int k = 0; k < 16; k++) {
            float4 a4 = *(const float4*)&As[k][ty * 4];
            float4 b4 = *(const float4*)&Bs[k][tx * 4];
            float ar[4] = {a4.x, a4.y, a4.z, a4.w};
            float br[4] = {b4.x, b4.y, b4.z, b4.w};
#pragma unroll
            for (int i = 0; i < 4; i++)
#pragma unroll
                for (int j = 0; j < 4; j++) acc[i][j] += ar[i] * br[j];
        }
        __syncthreads();
    }

#pragma unroll
    for (int i = 0; i < 4; i++) {
        int m = m0 + ty * 4 + i;
#pragma unroll
        for (int j = 0; j < 4; j++) {
            int a = n0 + tx * 4 + j;
            float bias = isPL ? g_posW[(m % HLv) * ATTv + a] : g_t0[a];
            C[m * ATTv + a] = acc[i][j] + bias;
        }
    }
}

// ---------------- K3: logits + softmax + output GEMM -----------------------
// One CTA per (b, 4 n's) -> grid 1024 (≈7 CTAs/SM) for latency hiding.
// Scalar FFMA throughout (regs ~36); unmasked-h compaction balances warps.
#define N_PER_CTA 4

__global__ __launch_bounds__(256) void attn_kernel(const float* __restrict__ logv,
                                                   const int*   __restrict__ mask,
                                                   const float* __restrict__ pos_emb,
                                                   const float* __restrict__ W2,
                                                   const float* __restrict__ b2,
                                                   float* __restrict__ out) {
    const int b = blockIdx.y;
    const int nbase = blockIdx.x * N_PER_CTA;

    __shared__ __align__(16) float pnS[N_PER_CTA][ATTv];    // 4 KB
    __shared__ float attnS[N_PER_CTA][HLv + 2];             // logits -> attn
    __shared__ int maskS[HLv];
    __shared__ short listS[HLv];
    __shared__ int cntS;

    const int tid = threadIdx.x;
    const int w = tid >> 5, lane = tid & 31;

    // pn tile: 4 rows x 256 = 256 float4, one per thread
    ((float4*)&pnS[0][0])[tid] =
        ((const float4*)(g_PN + (size_t)(b * NNv + nbase) * ATTv))[tid];
    if (tid < HLv) maskS[tid] = mask[b * HLv + tid];

    // W2 into registers (strided per lane; L1-cached broadcast across warps)
    float w2r[8];
#pragma unroll
    for (int i = 0; i < 8; i++) w2r[i] = W2[lane + 32 * i];
    const float b2v = b2[0];
    __syncthreads();

    // compact unmasked h list (thread 0); others init masked logits
    if (tid == 0) {
        int c = 0;
        for (int h = 0; h < HLv; h++)
            if (maskS[h] != 0) listS[c++] = (short)h;
        cntS = c;
    }
    if (tid < HLv && maskS[tid] == 0) {
#pragma unroll
        for (int n = 0; n < N_PER_CTA; n++) attnS[n][tid] = -1e9f;
    }
    __syncthreads();
    const int cnt = cntS;

    // ---- logits over compacted h: balanced across 8 warps ----
    for (int idx = w; idx < cnt; idx += 8) {
        const int h = listS[idx];
        const float* pl = g_PL + (size_t)(b * HLv + h) * ATTv;
        float plr[8];
#pragma unroll
        for (int i = 0; i < 8; i++) plr[i] = pl[lane + 32 * i];  // coalesced

        float s[N_PER_CTA];
#pragma unroll
        for (int n = 0; n < N_PER_CTA; n++) s[n] = 0.f;
#pragma unroll
        for (int i = 0; i < 8; i++) {
            const float pv = plr[i];
            const float wv = w2r[i];
            const int a = lane + 32 * i;
#pragma unroll
            for (int n = 0; n < N_PER_CTA; n++)
                s[n] += wv * tanh_fast(pv + pnS[n][a]);
        }
#pragma unroll
        for (int n = 0; n < N_PER_CTA; n++) {
            float v = s[n];
#pragma unroll
            for (int o = 16; o > 0; o >>= 1) v += __shfl_xor_sync(0xffffffffu, v, o);
            if (lane == 0) attnS[n][h] = v + b2v;
        }
    }
    __syncthreads();

    // ---- softmax: warp n (n<4) handles row n. All-masked -> uniform (jax). ----
    if (w < N_PER_CTA) {
        float v0 = attnS[w][lane];
        bool has1 = (lane + 32) < HLv;
        float v1 = has1 ? attnS[w][lane + 32] : -1e30f;
        float mx = fmaxf(v0, v1);
#pragma unroll
        for (int o = 16; o > 0; o >>= 1) mx = fmaxf(mx, __shfl_xor_sync(0xffffffffu, mx, o));
        float e0 = __expf(v0 - mx);
        float e1 = has1 ? __expf(v1 - mx) : 0.f;
        float ssum = e0 + e1;
#pragma unroll
        for (int o = 16; o > 0; o >>= 1) ssum += __shfl_xor_sync(0xffffffffu, ssum, o);
        float inv = 1.f / ssum;
        attnS[w][lane] = e0 * inv;
        if (has1) attnS[w][lane + 32] = e1 * inv;
    }
    __syncthreads();

    // ---- output: out[b, nbase+n, d] = sum_h attn[n,h] * lf[b,h,d] ----
    // lf[b,h,d] = d<384 ? log_vec[b,h,d] : pos_emb[1+h, d-384] (never materialized)
    float* obase = out + (size_t)(b * NNv + nbase) * NEWSv;
    for (int d = tid; d < NEWSv; d += 256) {
        float acc[N_PER_CTA];
#pragma unroll
        for (int j = 0; j < N_PER_CTA; j++) acc[j] = 0.f;

        const float* srcp;
        int stride;
        if (d < INv) { srcp = logv + (size_t)b * HLv * INv + d; stride = INv; }
        else         { srcp = pos_emb + POSv + (d - INv);       stride = POSv; }

#pragma unroll 5
        for (int h = 0; h < HLv; h++) {
            float lv = srcp[h * stride];
#pragma unroll
            for (int j = 0; j < N_PER_CTA; j++) acc[j] += attnS[j][h] * lv;
        }
#pragma unroll
        for (int j = 0; j < N_PER_CTA; j++)
            obase[(size_t)j * NEWSv + d] = acc[j];
    }
}

// ---------------- launch ----------------
extern "C" void kernel_launch(void* const* d_in, const int* in_sizes, int n_in,
                              void* d_out, int out_size) {
    const float* logv = (const float*)d_in[0];   // [64,50,384]
    const int*   mask = (const int*)  d_in[1];   // [64,50]
    const float* news = (const float*)d_in[2];   // [64,64,384]
    const float* pos  = (const float*)d_in[3];   // [100,64]
    const float* W1   = (const float*)d_in[4];   // [256,896]
    const float* b1   = (const float*)d_in[5];   // [256]
    const float* W2   = (const float*)d_in[6];   // [1,256]
    const float* b2   = (const float*)d_in[7];   // [1]

    float* out_user = (float*)d_out;                       // [64,64,448]
    float* out_nf   = out_user + (size_t)BB * NNv * NEWSv; // [64,64,448]

    prep_kernel<<<51, 256>>>(pos, W1, b1);
    nf_kernel<<<BB * NNv, 128>>>((const float4*)news, (const float4*)pos,
                                 (float4*)out_nf);
    gemm_kernel<<<dim3(4, 64, 2), 256>>>(news, logv, W1);
    attn_kernel<<<dim3(NNv / N_PER_CTA, BB), 256>>>(logv, mask, pos, W2, b2, out_user);
}

// round 15
// speedup vs baseline: 1.4840x; 1.1508x over previous
#include <cuda_runtime.h>

// ---------------- problem constants ----------------
#define BB    64    // batch
#define NNv   64    // news per batch
#define HLv   50    // history length
#define INv   384   // input dim
#define POSv  64    // pos-emb dim
#define ATTv  256   // attention hidden dim
#define NEWSv 448   // IN + POS
#define W1LD  896   // W1 row stride (2*NEWS)

// ---------------- device scratch (no allocations allowed) ----------------
__device__ float g_PN[BB * NNv * ATTv];    // 4 MB  : pn + t0   [4096, 256]
__device__ float g_PL[BB * HLv * ATTv];    // 3.3 MB: pl + posW [3200, 256]
__device__ float g_t0[ATTv];               // b1 + pos0 @ Wn_pos
__device__ float g_posW[HLv * ATTv];       // pos_emb[1+h] @ Wl_pos
__device__ float g_W1hi[ATTv * W1LD];      // tf32-hi split of W1
__device__ float g_W1lo[ATTv * W1LD];      // tf32-lo split of W1

__device__ __forceinline__ float tanh_fast(float x) {
    float y;
    asm("tanh.approx.f32 %0, %1;" : "=f"(y) : "f"(x));
    return y;
}

__device__ __forceinline__ unsigned tf32_rna(float x) {
    unsigned u;
    asm("cvt.rna.tf32.f32 %0, %1;" : "=r"(u) : "f"(x));
    return u;
}

// c[4] += A(tf32 m16k8) * B(tf32 k8n8)
#define MMA_TF32(cc, aa, bb)                                                     \
    asm("mma.sync.aligned.m16n8k8.row.col.f32.tf32.tf32.f32 "                    \
        "{%0,%1,%2,%3}, {%4,%5,%6,%7}, {%8,%9}, {%0,%1,%2,%3};"                  \
        : "+f"(cc[0]), "+f"(cc[1]), "+f"(cc[2]), "+f"(cc[3])                     \
        : "r"(aa[0]), "r"(aa[1]), "r"(aa[2]), "r"(aa[3]), "r"(bb[0]), "r"(bb[1]))

// ---------------- K0: tiny precompute of t0 and posW ----------------
__global__ void prep_kernel(const float* __restrict__ pos_emb,
                            const float* __restrict__ W1,
                            const float* __restrict__ b1) {
    int a = threadIdx.x;  // 0..255
    if (blockIdx.x == 0) {
        float s = b1[a];
#pragma unroll
        for (int j = 0; j < POSv; j++)
            s += pos_emb[j] * W1[a * W1LD + INv + j];
        g_t0[a] = s;
    } else {
        int h = blockIdx.x - 1;  // 0..49
        float s = 0.f;
#pragma unroll
        for (int j = 0; j < POSv; j++)
            s += pos_emb[(1 + h) * POSv + j] * W1[a * W1LD + NEWSv + INv + j];
        g_posW[h * ATTv + a] = s;
    }
}

// ---------------- K0b: pre-split W1 into tf32 hi/lo ----------------
__global__ void split_w1_kernel(const float* __restrict__ W1) {
    int a = blockIdx.x;            // 0..255
    int c = threadIdx.x * 4;       // 0..892
    if (c >= W1LD) return;
    float4 v = *(const float4*)(W1 + (size_t)a * W1LD + c);
    float h0 = __uint_as_float(tf32_rna(v.x));
    float h1 = __uint_as_float(tf32_rna(v.y));
    float h2 = __uint_as_float(tf32_rna(v.z));
    float h3 = __uint_as_float(tf32_rna(v.w));
    float l0 = __uint_as_float(tf32_rna(v.x - h0));
    float l1 = __uint_as_float(tf32_rna(v.y - h1));
    float l2 = __uint_as_float(tf32_rna(v.z - h2));
    float l3 = __uint_as_float(tf32_rna(v.w - h3));
    *(float4*)(g_W1hi + (size_t)a * W1LD + c) = make_float4(h0, h1, h2, h3);
    *(float4*)(g_W1lo + (size_t)a * W1LD + c) = make_float4(l0, l1, l2, l3);
}

// ---------------- K1: nf output (pure copy/broadcast, float4) ----------------
__global__ void nf_kernel(const float4* __restrict__ news4,
                          const float4* __restrict__ pos4,
                          float4* __restrict__ out4) {
    int bn = blockIdx.x;      // 0..4095
    int d4 = threadIdx.x;     // 0..111
    if (d4 >= NEWSv / 4) return;
    float4 v = (d4 < INv / 4) ? news4[bn * (INv / 4) + d4] : pos4[d4 - INv / 4];
    out4[bn * (NEWSv / 4) + d4] = v;
}

// ---------------- K2: tensor-core GEMMs, 3xTF32 (z=0: PN, z=1: PL) ----------
// C[m,a] = sum_k A[m,k] * W1[a, colofs+k] + bias, fp32-grade via
// C = Ahi*Bhi + Ahi*Blo + Alo*Bhi. CTA tile 64x64, 4 warps (2x2), KC=16.
#define KC  16
#define SLD 20   // smem row stride (floats); conflict-free for frag patterns

__global__ __launch_bounds__(128) void gemm_tc_kernel(const float* __restrict__ news,
                                                      const float* __restrict__ logv) {
    const int isPL = blockIdx.z;
    const float* A;
    float* C;
    int colofs;
    if (isPL) {
        if (blockIdx.y >= 50) return;
        A = logv; C = g_PL; colofs = NEWSv;
    } else {
        A = news; C = g_PN; colofs = 0;
    }
    const int m0 = blockIdx.y * 64;
    const int n0 = blockIdx.x * 64;

    __shared__ __align__(16) float Ah[64 * SLD], Al[64 * SLD];
    __shared__ __align__(16) float Bh[64 * SLD], Bl[64 * SLD];

    const int tid = threadIdx.x;
    const int wid = tid >> 5, lane = tid & 31;
    const int wm = wid >> 1, wn = wid & 1;       // 2x2 warp grid
    const int g = lane >> 2, tg = lane & 3;      // groupID, threadInGroup

    const int lrow = tid >> 2;                   // 0..31
    const int lc4 = (tid & 3) * 4;               // 0,4,8,12

    float c[2][4][4];
#pragma unroll
    for (int mt = 0; mt < 2; mt++)
#pragma unroll
        for (int nt = 0; nt < 4; nt++)
#pragma unroll
            for (int i = 0; i < 4; i++) c[mt][nt][i] = 0.f;

    for (int kc = 0; kc < INv; kc += KC) {
#pragma unroll
        for (int half = 0; half < 2; half++) {
            const int row = lrow + half * 32;
            // A: load + split
            float4 v = *(const float4*)(A + (size_t)(m0 + row) * INv + kc + lc4);
            float h0 = __uint_as_float(tf32_rna(v.x));
            float h1 = __uint_as_float(tf32_rna(v.y));
            float h2 = __uint_as_float(tf32_rna(v.z));
            float h3 = __uint_as_float(tf32_rna(v.w));
            *(float4*)(Ah + row * SLD + lc4) = make_float4(h0, h1, h2, h3);
            *(float4*)(Al + row * SLD + lc4) = make_float4(
                __uint_as_float(tf32_rna(v.x - h0)), __uint_as_float(tf32_rna(v.y - h1)),
                __uint_as_float(tf32_rna(v.z - h2)), __uint_as_float(tf32_rna(v.w - h3)));
            // B: pre-split
            *(float4*)(Bh + row * SLD + lc4) =
                *(const float4*)(g_W1hi + (size_t)(n0 + row) * W1LD + colofs + kc + lc4);
            *(float4*)(Bl + row * SLD + lc4) =
                *(const float4*)(g_W1lo + (size_t)(n0 + row) * W1LD + colofs + kc + lc4);
        }
        __syncthreads();

#pragma unroll
        for (int ks = 0; ks < 2; ks++) {
            const int kb = ks * 8;
            unsigned ah[2][4], al[2][4];
#pragma unroll
            for (int mt = 0; mt < 2; mt++) {
                const int r = wm * 32 + mt * 16 + g;
                ah[mt][0] = __float_as_uint(Ah[r * SLD + kb + tg]);
                ah[mt][1] = __float_as_uint(Ah[(r + 8) * SLD + kb + tg]);
                ah[mt][2] = __float_as_uint(Ah[r * SLD + kb + tg + 4]);
                ah[mt][3] = __float_as_uint(Ah[(r + 8) * SLD + kb + tg + 4]);
                al[mt][0] = __float_as_uint(Al[r * SLD + kb + tg]);
                al[mt][1] = __float_as_uint(Al[(r + 8) * SLD + kb + tg]);
                al[mt][2] = __float_as_uint(Al[r * SLD + kb + tg + 4]);
                al[mt][3] = __float_as_uint(Al[(r + 8) * SLD + kb + tg + 4]);
            }
            unsigned bh[4][2], bl[4][2];
#pragma unroll
            for (int nt = 0; nt < 4; nt++) {
                const int r = wn * 32 + nt * 8 + g;
                bh[nt][0] = __float_as_uint(Bh[r * SLD + kb + tg]);
                bh[nt][1] = __float_as_uint(Bh[r * SLD + kb + tg + 4]);
                bl[nt][0] = __float_as_uint(Bl[r * SLD + kb + tg]);
                bl[nt][1] = __float_as_uint(Bl[r * SLD + kb + tg + 4]);
            }
#pragma unroll
            for (int mt = 0; mt < 2; mt++)
#pragma unroll
                for (int nt = 0; nt < 4; nt++) {
                    MMA_TF32(c[mt][nt], ah[mt], bh[nt]);
                    MMA_TF32(c[mt][nt], ah[mt], bl[nt]);
                    MMA_TF32(c[mt][nt], al[mt], bh[nt]);
                }
        }
        __syncthreads();
    }

    // epilogue: c0,c1 -> (row g, cols 2tg,2tg+1); c2,c3 -> row g+8
#pragma unroll
    for (int mt = 0; mt < 2; mt++) {
        const int m1 = m0 + wm * 32 + mt * 16 + g;
        const int m2 = m1 + 8;
        const float* bp1 = isPL ? (g_posW + (m1 % HLv) * ATTv) : g_t0;
        const float* bp2 = isPL ? (g_posW + (m2 % HLv) * ATTv) : g_t0;
#pragma unroll
        for (int nt = 0; nt < 4; nt++) {
            const int a = n0 + wn * 32 + nt * 8 + 2 * tg;
            *(float2*)(C + (size_t)m1 * ATTv + a) =
                make_float2(c[mt][nt][0] + bp1[a], c[mt][nt][1] + bp1[a + 1]);
            *(float2*)(C + (size_t)m2 * ATTv + a) =
                make_float2(c[mt][nt][2] + bp2[a], c[mt][nt][3] + bp2[a + 1]);
        }
    }
}

// ---------------- K3: logits + softmax + output GEMM (R11, proven) ---------
#define N_PER_CTA 4

__global__ __launch_bounds__(256) void attn_kernel(const float* __restrict__ logv,
                                                   const int*   __restrict__ mask,
                                                   const float* __restrict__ pos_emb,
                                                   const float* __restrict__ W2,
                                                   const float* __restrict__ b2,
                                                   float* __restrict__ out) {
    const int b = blockIdx.y;
    const int nbase = blockIdx.x * N_PER_CTA;

    __shared__ __align__(16) float pnS[N_PER_CTA][ATTv];
    __shared__ float attnS[N_PER_CTA][HLv + 2];
    __shared__ int maskS[HLv];
    __shared__ short listS[HLv];
    __shared__ int cntS;

    const int tid = threadIdx.x;
    const int w = tid >> 5, lane = tid & 31;

    ((float4*)&pnS[0][0])[tid] =
        ((const float4*)(g_PN + (size_t)(b * NNv + nbase) * ATTv))[tid];
    if (tid < HLv) maskS[tid] = mask[b * HLv + tid];

    float w2r[8];
#pragma unroll
    for (int i = 0; i < 8; i++) w2r[i] = W2[lane + 32 * i];
    const float b2v = b2[0];
    __syncthreads();

    if (tid == 0) {
        int c = 0;
        for (int h = 0; h < HLv; h++)
            if (maskS[h] != 0) listS[c++] = (short)h;
        cntS = c;
    }
    if (tid < HLv && maskS[tid] == 0) {
#pragma unroll
        for (int n = 0; n < N_PER_CTA; n++) attnS[n][tid] = -1e9f;
    }
    __syncthreads();
    const int cnt = cntS;

    for (int idx = w; idx < cnt; idx += 8) {
        const int h = listS[idx];
        const float* pl = g_PL + (size_t)(b * HLv + h) * ATTv;
        float plr[8];
#pragma unroll
        for (int i = 0; i < 8; i++) plr[i] = pl[lane + 32 * i];

        float s[N_PER_CTA];
#pragma unroll
        for (int n = 0; n < N_PER_CTA; n++) s[n] = 0.f;
#pragma unroll
        for (int i = 0; i < 8; i++) {
            const float pv = plr[i];
            const float wv = w2r[i];
            const int a = lane + 32 * i;
#pragma unroll
            for (int n = 0; n < N_PER_CTA; n++)
                s[n] += wv * tanh_fast(pv + pnS[n][a]);
        }
#pragma unroll
        for (int n = 0; n < N_PER_CTA; n++) {
            float v = s[n];
#pragma unroll
            for (int o = 16; o > 0; o >>= 1) v += __shfl_xor_sync(0xffffffffu, v, o);
            if (lane == 0) attnS[n][h] = v + b2v;
        }
    }
    __syncthreads();

    if (w < N_PER_CTA) {
        float v0 = attnS[w][lane];
        bool has1 = (lane + 32) < HLv;
        float v1 = has1 ? attnS[w][lane + 32] : -1e30f;
        float mx = fmaxf(v0, v1);
#pragma unroll
        for (int o = 16; o > 0; o >>= 1) mx = fmaxf(mx, __shfl_xor_sync(0xffffffffu, mx, o));
        float e0 = __expf(v0 - mx);
        float e1 = has1 ? __expf(v1 - mx) : 0.f;
        float ssum = e0 + e1;
#pragma unroll
        for (int o = 16; o > 0; o >>= 1) ssum += __shfl_xor_sync(0xffffffffu, ssum, o);
        float inv = 1.f / ssum;
        attnS[w][lane] = e0 * inv;
        if (has1) attnS[w][lane + 32] = e1 * inv;
    }
    __syncthreads();

    float* obase = out + (size_t)(b * NNv + nbase) * NEWSv;
    for (int d = tid; d < NEWSv; d += 256) {
        float acc[N_PER_CTA];
#pragma unroll
        for (int j = 0; j < N_PER_CTA; j++) acc[j] = 0.f;

        const float* srcp;
        int stride;
        if (d < INv) { srcp = logv + (size_t)b * HLv * INv + d; stride = INv; }
        else         { srcp = pos_emb + POSv + (d - INv);       stride = POSv; }

#pragma unroll 5
        for (int h = 0; h < HLv; h++) {
            float lv = srcp[h * stride];
#pragma unroll
            for (int j = 0; j < N_PER_CTA; j++) acc[j] += attnS[j][h] * lv;
        }
#pragma unroll
        for (int j = 0; j < N_PER_CTA; j++)
            obase[(size_t)j * NEWSv + d] = acc[j];
    }
}

// ---------------- launch ----------------
extern "C" void kernel_launch(void* const* d_in, const int* in_sizes, int n_in,
                              void* d_out, int out_size) {
    const float* logv = (const float*)d_in[0];   // [64,50,384]
    const int*   mask = (const int*)  d_in[1];   // [64,50]
    const float* news = (const float*)d_in[2];   // [64,64,384]
    const float* pos  = (const float*)d_in[3];   // [100,64]
    const float* W1   = (const float*)d_in[4];   // [256,896]
    const float* b1   = (const float*)d_in[5];   // [256]
    const float* W2   = (const float*)d_in[6];   // [1,256]
    const float* b2   = (const float*)d_in[7];   // [1]

    float* out_user = (float*)d_out;                       // [64,64,448]
    float* out_nf   = out_user + (size_t)BB * NNv * NEWSv; // [64,64,448]

    prep_kernel<<<51, 256>>>(pos, W1, b1);
    split_w1_kernel<<<ATTv, 224>>>(W1);
    nf_kernel<<<BB * NNv, 128>>>((const float4*)news, (const float4*)pos,
                                 (float4*)out_nf);
    gemm_tc_kernel<<<dim3(4, 64, 2), 128>>>(news, logv);
    attn_kernel<<<dim3(NNv / N_PER_CTA, BB), 256>>>(logv, mask, pos, W2, b2, out_user);
}